// round 8
// baseline (speedup 1.0000x reference)
#include <cuda_runtime.h>
#include <cuda_fp16.h>

#define NB 128
#define NB3 (NB * NB * NB)

// Slice table, x FASTEST: slice s = ((iy*NB)+iz)*NB+ix, 32B each (2 uint4):
//   g_slices[2s+0] = { G(ix,iy,iz),   G(ix,iy+1,iz)   } 4ch fp16 each (y-pair @ z)
//   g_slices[2s+1] = { G(ix,iy,iz+1), G(ix,iy+1,iz+1) }            (y-pair @ z+1)
// (y+1, z+1 clamped at 127 during build.)
// A point reads the contiguous 64B window [32*cell, 32*cell+64) covering
// slices ix0 and ix0+1 -> 1 cache line 75% of the time (1.25 wf/point avg).
// +8 uint4 padding: the ix0=127 window overruns 32B with zero weight (fx=0).
__device__ uint4 g_slices[NB3 * 2 + 8];

__device__ __forceinline__ uint4 pack_ypair(float4 a, float4 b)
{
    __half2 h0 = __floats2half2_rn(a.x, a.y);
    __half2 h1 = __floats2half2_rn(a.z, a.w);
    __half2 h2 = __floats2half2_rn(b.x, b.y);
    __half2 h3 = __floats2half2_rn(b.z, b.w);
    uint4 v;
    v.x = *reinterpret_cast<const unsigned int*>(&h0);
    v.y = *reinterpret_cast<const unsigned int*>(&h1);
    v.z = *reinterpret_cast<const unsigned int*>(&h2);
    v.w = *reinterpret_cast<const unsigned int*>(&h3);
    return v;
}

// Transpose build: block = (iy, 16-wide ix tile). Phase 1 reads grid rows
// coalesced along z and packs y-pairs into SMEM; phase 2 writes slices
// coalesced along x (2 x STG.128 per slice, fully-covered lines).
#define TX 16
#define ROWP 129   // 128 entries + 1 uint4 pad per row -> conflict-free LDS

__global__ __launch_bounds__(256)
void build_slices_kernel(const float4* __restrict__ grid)
{
    __shared__ uint4 P[TX * ROWP];   // 33 KB

    int iy = blockIdx.x >> 3;
    int X0 = (blockIdx.x & 7) * TX;
    int iyp = min(iy + 1, NB - 1);

    int t  = threadIdx.x;
    int tz = t & 127;
    int th = t >> 7;   // 0..1

    // Phase 1: pack y-pairs P[ixl][z] = {G(ix,iy,z), G(ix,iy+1,z)}
    #pragma unroll
    for (int ixl = th; ixl < TX; ixl += 2) {
        int ix = X0 + ixl;
        float4 a = grid[(ix * NB + iy)  * NB + tz];
        float4 b = grid[(ix * NB + iyp) * NB + tz];
        P[ixl * ROWP + tz] = pack_ypair(a, b);
    }
    __syncthreads();

    // Phase 2: slice s = ((iy*NB)+iz)*NB + X0+ixl;
    //   chunk0 = P[ixl][iz], chunk1 = P[ixl][min(iz+1,127)]
    int ixl = t & (TX - 1);
    int izb = t >> 4;   // 0..15
    #pragma unroll
    for (int iz = izb; iz < NB; iz += 16) {
        uint4 c0 = P[ixl * ROWP + iz];
        uint4 c1 = P[ixl * ROWP + min(iz + 1, NB - 1)];
        int s = (iy * NB + iz) * NB + X0 + ixl;
        g_slices[2 * s + 0] = c0;
        g_slices[2 * s + 1] = c1;
    }
}

// y-lerp of one 16B chunk (2 corners x 4ch fp16)
__device__ __forceinline__ float4 ylerp(uint4 p, float wy0, float wy1)
{
    float2 axy = __half22float2(*reinterpret_cast<const __half2*>(&p.x));
    float2 azw = __half22float2(*reinterpret_cast<const __half2*>(&p.y));
    float2 bxy = __half22float2(*reinterpret_cast<const __half2*>(&p.z));
    float2 bzw = __half22float2(*reinterpret_cast<const __half2*>(&p.w));

    float4 r;
    r.x = fmaf(wy1, bxy.x, wy0 * axy.x);
    r.y = fmaf(wy1, bxy.y, wy0 * axy.y);
    r.z = fmaf(wy1, bzw.x, wy0 * azw.x);
    r.w = fmaf(wy1, bzw.y, wy0 * azw.y);
    return r;
}

struct PSetup {
    int  u4;        // uint4 index of this lane's chunk: 2*cell + l
    float fy, wv;   // wv = wx(xs) * wz(zs) for this lane
};

__device__ __forceinline__ PSetup make_setup(float px, float py, float pz,
                                             int xs, int zs, int l)
{
    px = fminf(fmaxf(px * (float)NB, 0.0f), (float)(NB - 1));
    py = fminf(fmaxf(py * (float)NB, 0.0f), (float)(NB - 1));
    pz = fminf(fmaxf(pz * (float)NB, 0.0f), (float)(NB - 1));

    int ix0 = (int)floorf(px);
    int iy0 = (int)floorf(py);
    int iz0 = (int)floorf(pz);

    float fx = px - (float)ix0;
    float fz = pz - (float)iz0;

    PSetup s;
    s.fy = py - (float)iy0;
    float wx = xs ? fx : (1.0f - fx);
    float wz = zs ? fz : (1.0f - fz);
    s.wv = wx * wz;

    int cell = (iy0 * NB + iz0) * NB + ix0;
    s.u4 = 2 * cell + l;   // contiguous 64B window; l=2,3 land in slice ix0+1
    return s;
}

// Weighted partial for this lane, then 3-shfl butterfly: lane l ends with
// channel l of the point's output summed over all 4 lanes.
__device__ __forceinline__ float finish(uint4 A, const PSetup& s, int xs, int zs)
{
    float wy1 = s.fy, wy0 = 1.0f - s.fy;
    float4 m = ylerp(A, wy0, wy1);
    float4 r;
    r.x = s.wv * m.x;
    r.y = s.wv * m.y;
    r.z = s.wv * m.z;
    r.w = s.wv * m.w;

    // stage 1 (xor 2, combine x): xs=0 keeps ch{0,1}, xs=1 keeps ch{2,3}
    float v0 = xs ? r.x : r.z;
    float v1 = xs ? r.y : r.w;
    float t0 = __shfl_xor_sync(0xFFFFFFFFu, v0, 2);
    float t1 = __shfl_xor_sync(0xFFFFFFFFu, v1, 2);
    float s0 = (xs ? r.z : r.x) + t0;
    float s1 = (xs ? r.w : r.y) + t1;

    // stage 2 (xor 1, combine z): zs=0 keeps s0, zs=1 keeps s1
    float v2 = zs ? s0 : s1;
    float t2 = __shfl_xor_sync(0xFFFFFFFFu, v2, 1);
    return (zs ? s1 : s0) + t2;   // channel 2*xs + zs == l
}

// 4 lanes per point, 2 points per thread (p, p+h): 2 gathers in flight.
__global__ __launch_bounds__(256, 6)
void interp_slice_kernel(const float* __restrict__ x,
                         float* __restrict__ out,   // [N,4] as flat floats
                         int n, int h)
{
    int tid = blockIdx.x * blockDim.x + threadIdx.x;
    int l   = tid & 3;
    int p0  = tid >> 2;
    int xs  = l >> 1;
    int zs  = l & 1;

    bool v0 = (p0 < h);
    int c0 = v0 ? p0 : 0;
    int p1 = c0 + h;
    bool v1 = v0 && (p1 < n);
    int c1 = v1 ? p1 : c0;

    float ax = x[3 * c0 + 0];
    float ay = x[3 * c0 + 1];
    float az = x[3 * c0 + 2];
    float bx = x[3 * c1 + 0];
    float by = x[3 * c1 + 1];
    float bz = x[3 * c1 + 2];

    PSetup S0 = make_setup(ax, ay, az, xs, zs, l);
    PSetup S1 = make_setup(bx, by, bz, xs, zs, l);

    // Two gathers back-to-back; each quad of lanes covers one 64B window
    // (1 line 75% / 2 lines 25% -> 1.25 wf per point per instruction).
    uint4 A0 = __ldg(&g_slices[S0.u4]);
    uint4 A1 = __ldg(&g_slices[S1.u4]);

    float o0 = finish(A0, S0, xs, zs);
    float o1 = finish(A1, S1, xs, zs);

    if (v0) out[4 * p0 + l] = o0;   // 32 consecutive floats per warp
    if (v1) out[4 * p1 + l] = o1;
}

extern "C" void kernel_launch(void* const* d_in, const int* in_sizes, int n_in,
                              void* d_out, int out_size)
{
    const float*  x    = (const float*)d_in[0];   // [N,3] float32
    const float4* grid = (const float4*)d_in[1];  // [128,128,128,4] float32
    float*        out  = (float*)d_out;           // [N,4] float32

    int n = in_sizes[0] / 3;
    int h = (n + 1) / 2;

    build_slices_kernel<<<NB * 8, 256>>>(grid);

    long long threads = 4LL * h;
    int grid_dim = (int)((threads + 255) / 256);
    interp_slice_kernel<<<grid_dim, 256>>>(x, out, n, h);
}

// round 10
// speedup vs baseline: 1.5290x; 1.5290x over previous
#include <cuda_runtime.h>
#include <cuda_fp16.h>

#define NB 128
#define NB3 (NB * NB * NB)

// y-pair table: P[ix][iy][iz] = { G(ix,iy,iz) 4xfp16, G(ix,min(iy+1,127),iz) 4xfp16 }
// 16 B/entry, 33.5 MB -> L2-resident (pinned via evict_last policy on the gather path).
// z-neighbors are ADJACENT entries, so a lane pair covering (iz0, iz0+1) hits
// one 128B line per instruction.
__device__ uint4 g_ypairs[NB3];

__device__ __forceinline__ uint2 pack_h4(float4 v)
{
    __half2 h0 = __floats2half2_rn(v.x, v.y);
    __half2 h1 = __floats2half2_rn(v.z, v.w);
    uint2 r;
    r.x = *reinterpret_cast<const unsigned int*>(&h0);
    r.y = *reinterpret_cast<const unsigned int*>(&h1);
    return r;
}

__global__ __launch_bounds__(256)
void build_ypairs_kernel(const float4* __restrict__ grid)
{
    int idx = blockIdx.x * blockDim.x + threadIdx.x;
    if (idx >= NB3) return;

    int iy = (idx >> 7) & (NB - 1);
    int dy = (iy < NB - 1) ? NB : 0;

    float4 a = grid[idx];        // (ix, iy,   iz)
    float4 b = grid[idx + dy];   // (ix, iy+1, iz) clamped

    uint2 pa = pack_h4(a);
    uint2 pb = pack_h4(b);

    uint4 v;
    v.x = pa.x; v.y = pa.y; v.z = pb.x; v.w = pb.y;
    g_ypairs[idx] = v;
}

// evict_last cache policy (created once per thread, reused for all gathers)
__device__ __forceinline__ unsigned long long make_evict_last_policy()
{
    unsigned long long pol;
    asm("createpolicy.fractional.L2::evict_last.b64 %0, 1.0;" : "=l"(pol));
    return pol;
}

// Table gather with L2 evict_last hint: keeps the 33.5MB table resident
// against the once-touched x/out streams.
__device__ __forceinline__ uint4 ldg_pin(const uint4* p, unsigned long long pol)
{
    uint4 v;
    asm("ld.global.nc.L2::cache_hint.v4.u32 {%0,%1,%2,%3}, [%4], %5;"
        : "=r"(v.x), "=r"(v.y), "=r"(v.z), "=r"(v.w)
        : "l"(p), "l"(pol));
    return v;
}

// y-lerp of one entry: corner_y0*wy0 + corner_y1*wy1
__device__ __forceinline__ float4 ylerp(uint4 p, float wy0, float wy1)
{
    float2 axy = __half22float2(*reinterpret_cast<const __half2*>(&p.x));
    float2 azw = __half22float2(*reinterpret_cast<const __half2*>(&p.y));
    float2 bxy = __half22float2(*reinterpret_cast<const __half2*>(&p.z));
    float2 bzw = __half22float2(*reinterpret_cast<const __half2*>(&p.w));

    float4 r;
    r.x = fmaf(wy1, bxy.x, wy0 * axy.x);
    r.y = fmaf(wy1, bxy.y, wy0 * axy.y);
    r.z = fmaf(wy1, bzw.x, wy0 * azw.x);
    r.w = fmaf(wy1, bzw.y, wy0 * azw.y);
    return r;
}

struct Setup {
    int e0, e1;        // table entries for this lane's z-slice (x0, x1 cells)
    float fx, fy, wz;  // wz = this lane's z weight
};

__device__ __forceinline__ Setup make_setup(float px, float py, float pz, int q)
{
    px = fminf(fmaxf(px * (float)NB, 0.0f), (float)(NB - 1));
    py = fminf(fmaxf(py * (float)NB, 0.0f), (float)(NB - 1));
    pz = fminf(fmaxf(pz * (float)NB, 0.0f), (float)(NB - 1));

    int ix0 = (int)floorf(px);
    int iy0 = (int)floorf(py);
    int iz0 = (int)floorf(pz);

    Setup s;
    s.fx = px - (float)ix0;
    s.fy = py - (float)iy0;
    float fz = pz - (float)iz0;
    s.wz = q ? fz : (1.0f - fz);

    int ix1 = min(ix0 + 1, NB - 1);
    int izq = min(iz0 + q, NB - 1);

    s.e0 = (ix0 * NB + iy0) * NB + izq;
    s.e1 = (ix1 * NB + iy0) * NB + izq;
    return s;
}

// Partial result for this lane's z-slice (all 4 channels, weighted by wz).
__device__ __forceinline__ float4 lane_partial(uint4 A, uint4 B, const Setup& s)
{
    float wy1 = s.fy, wy0 = 1.0f - s.fy;
    float4 m0 = ylerp(A, wy0, wy1);
    float4 m1 = ylerp(B, wy0, wy1);

    float wx1 = s.fx, wx0 = 1.0f - s.fx;
    float4 r;
    r.x = s.wz * fmaf(wx1, m1.x, wx0 * m0.x);
    r.y = s.wz * fmaf(wx1, m1.y, wx0 * m0.y);
    r.z = s.wz * fmaf(wx1, m1.z, wx0 * m0.z);
    r.w = s.wz * fmaf(wx1, m1.w, wx0 * m0.w);
    return r;
}

// Half-exchange: lane0 finalizes {x,y}, lane1 finalizes {z,w}; 2 shfls/point.
__device__ __forceinline__ float2 reduce_half(float4 r, int q)
{
    float s1 = __shfl_xor_sync(0xFFFFFFFFu, q ? r.x : r.z, 1);
    float s2 = __shfl_xor_sync(0xFFFFFFFFu, q ? r.y : r.w, 1);
    float2 o;
    if (q == 0) { o.x = r.x + s1; o.y = r.y + s2; }
    else        { o.x = r.z + s1; o.y = r.w + s2; }
    return o;
}

// 2 lanes per point, 2 points per lane-pair (p and p+half) -> 4 gathers in flight.
__global__ __launch_bounds__(256)
void interp_coop2_kernel(const float* __restrict__ x,
                         float2* __restrict__ out,   // [N,4] viewed as float2[2N]
                         int n, int half)
{
    int tid = blockIdx.x * blockDim.x + threadIdx.x;
    int p0  = tid >> 1;
    int q   = tid & 1;

    if (p0 >= half) return;
    int p1 = p0 + half;
    bool hasB = (p1 < n);
    int p1c = hasB ? p1 : p0;

    unsigned long long pol = make_evict_last_policy();

    // Streaming loads (evict-first): don't displace the pinned table in L2.
    float ax = __ldcs(&x[3 * p0 + 0]);
    float ay = __ldcs(&x[3 * p0 + 1]);
    float az = __ldcs(&x[3 * p0 + 2]);
    float bx = __ldcs(&x[3 * p1c + 0]);
    float by = __ldcs(&x[3 * p1c + 1]);
    float bz = __ldcs(&x[3 * p1c + 2]);

    Setup SA = make_setup(ax, ay, az, q);
    Setup SB = make_setup(bx, by, bz, q);

    // 4 gathers back-to-back; lane pairs hit 1 line per point per instruction.
    uint4 A0 = ldg_pin(&g_ypairs[SA.e0], pol);
    uint4 A1 = ldg_pin(&g_ypairs[SA.e1], pol);
    uint4 B0 = ldg_pin(&g_ypairs[SB.e0], pol);
    uint4 B1 = ldg_pin(&g_ypairs[SB.e1], pol);

    float4 ra = lane_partial(A0, A1, SA);
    float4 rb = lane_partial(B0, B1, SB);

    float2 oa = reduce_half(ra, q);
    float2 ob = reduce_half(rb, q);

    __stcs(&out[2 * p0 + q], oa);          // streaming store, pair writes 16B
    if (hasB)
        __stcs(&out[2 * p1 + q], ob);
}

extern "C" void kernel_launch(void* const* d_in, const int* in_sizes, int n_in,
                              void* d_out, int out_size)
{
    const float*  x    = (const float*)d_in[0];   // [N,3] float32
    const float4* grid = (const float4*)d_in[1];  // [128,128,128,4] float32
    float2*       out  = (float2*)d_out;          // [N,4] float32

    int n = in_sizes[0] / 3;
    int half = (n + 1) / 2;

    const int block = 256;
    build_ypairs_kernel<<<(NB3 + block - 1) / block, block>>>(grid);

    long long threads = 2LL * half;
    int grid_dim = (int)((threads + block - 1) / block);
    interp_coop2_kernel<<<grid_dim, block>>>(x, out, n, half);
}